// round 14
// baseline (speedup 1.0000x reference)
#include <cuda_runtime.h>
#include <cuda_fp16.h>
#include <math.h>
#include <stdint.h>

// ---------------- constants ----------------
constexpr int D_   = 256;
constexpr int H_   = 8;
constexpr int L_   = 4;
constexpr int P_   = 4;
constexpr int DFF_ = 2048;
constexpr int DH_  = 32;
constexpr int NQ_  = 900;
constexpr int B_   = 8;
constexpr int S_   = 12240;
constexpr int NR_  = NQ_ * B_;          // 7200 rows
constexpr int SQK  = 512;               // row stride of fused Q|K projection buffer
constexpr int NOAW = 384;               // fused offs(256) + aw(128) projection width

// ---------------- scratch (no allocations allowed) ----------------
__device__ __align__(256) float  g_SA   [NR_ * D_];
__device__ __align__(256) float  g_X1   [NR_ * D_];
__device__ __align__(256) float  g_OAW  [NR_ * NOAW];
__device__ __align__(256) float  g_CA   [NR_ * D_];
__device__ __align__(256) float  g_X2   [NR_ * D_];
__device__ __align__(256) float  g_FF   [NR_ * D_];
__device__ __align__(256) float  g_oab  [NOAW];
__device__ __align__(256) __half g_ADDQh[NR_ * D_];
__device__ __align__(256) __half g_Qh   [NR_ * D_];
__device__ __align__(256) __half g_MEMh [S_ * B_ * D_];
__device__ __align__(256) __half g_QKph [NR_ * SQK];
__device__ __align__(256) __half g_Vh   [NR_ * D_];
__device__ __align__(256) __half g_SAph [NR_ * D_];
__device__ __align__(256) __half g_QINh [NR_ * D_];
__device__ __align__(256) __half g_VALh [S_ * B_ * D_];
__device__ __align__(256) __half g_DOUTh[NR_ * D_];
__device__ __align__(256) __half g_X2h  [NR_ * D_];
__device__ __align__(256) __half g_HHh  [NR_ * DFF_];
__device__ __align__(256) __half g_inwh [3 * D_ * D_];
__device__ __align__(256) __half g_outwh[D_ * D_];
__device__ __align__(256) __half g_valwh[D_ * D_];
__device__ __align__(256) __half g_oawh [NOAW * D_];
__device__ __align__(256) __half g_cowh [D_ * D_];
__device__ __align__(256) __half g_l1wh [DFF_ * D_];
__device__ __align__(256) __half g_l2wh [D_ * DFF_];

// ---------------- helpers ----------------
__device__ __forceinline__ float blockReduceSum(float v) {
    __shared__ float red[32];
    int lane = threadIdx.x & 31;
    int wid  = threadIdx.x >> 5;
    #pragma unroll
    for (int o = 16; o > 0; o >>= 1) v += __shfl_xor_sync(0xffffffffu, v, o);
    if (lane == 0) red[wid] = v;
    __syncthreads();
    float r = (threadIdx.x < (blockDim.x >> 5)) ? red[threadIdx.x] : 0.f;
    if (wid == 0) {
        #pragma unroll
        for (int o = 16; o > 0; o >>= 1) r += __shfl_xor_sync(0xffffffffu, r, o);
        if (lane == 0) red[0] = r;
    }
    __syncthreads();
    r = red[0];
    __syncthreads();
    return r;
}

__device__ __forceinline__ uint32_t smem_u32(const void* p) {
    return (uint32_t)__cvta_generic_to_shared(p);
}

__device__ __forceinline__ void cp16(uint32_t dst, const void* src, int srcBytes) {
    asm volatile("cp.async.cg.shared.global [%0], [%1], 16, %2;\n"
                 :: "r"(dst), "l"(src), "r"(srcBytes));
}
#define CP_COMMIT() asm volatile("cp.async.commit_group;\n" ::: "memory")
template<int N_>
__device__ __forceinline__ void cp_wait() {
    asm volatile("cp.async.wait_group %0;\n" :: "n"(N_) : "memory");
}

// fp16 MMA, fp32 accumulate
#define MMA16(d, a, b2) asm volatile( \
    "mma.sync.aligned.m16n8k16.row.col.f32.f16.f16.f32 " \
    "{%0,%1,%2,%3}, {%4,%5,%6,%7}, {%8,%9}, {%0,%1,%2,%3};\n" \
    : "+f"((d)[0]), "+f"((d)[1]), "+f"((d)[2]), "+f"((d)[3]) \
    : "r"((a)[0]), "r"((a)[1]), "r"((a)[2]), "r"((a)[3]), \
      "r"((b2)[0]), "r"((b2)[1]))

// ---------------- f32 -> f16 batch convert ----------------
__global__ __launch_bounds__(256) void cvt_multi(const float* a0, __half* o0, int n0,
                                                 const float* a1, __half* o1, int n1,
                                                 const float* a2, __half* o2, int n2,
                                                 const float* a3, __half* o3, int n3) {
    int stride = gridDim.x * 256;
    int base = blockIdx.x * 256 + threadIdx.x;
    for (int i = base; i < n0; i += stride) o0[i] = __float2half_rn(a0[i]);
    for (int i = base; i < n1; i += stride) o1[i] = __float2half_rn(a1[i]);
    for (int i = base; i < n2; i += stride) o2[i] = __float2half_rn(a2[i]);
    for (int i = base; i < n3; i += stride) o3[i] = __float2half_rn(a3[i]);
}

__global__ __launch_bounds__(384) void pack_bias(const float* __restrict__ ob,
                                                 const float* __restrict__ ab,
                                                 float* __restrict__ dst) {
    int i = threadIdx.x;
    dst[i] = (i < 256) ? ob[i] : ab[i - 256];
}

__global__ __launch_bounds__(256) void add2q_kernel(const float* __restrict__ q,
                                                    const float* __restrict__ pos,
                                                    __half* __restrict__ addq,
                                                    __half* __restrict__ qh, int n) {
    int i = blockIdx.x * 256 + threadIdx.x;
    if (i < n) {
        float a = q[i];
        addq[i] = __float2half_rn(a + pos[i]);
        qh[i]   = __float2half_rn(a);
    }
}

__global__ __launch_bounds__(256) void add_ln_kernel(const float* __restrict__ a,
                                                     const float* __restrict__ b,
                                                     const float* __restrict__ gain,
                                                     const float* __restrict__ beta,
                                                     float* __restrict__ out,
                                                     const float* __restrict__ pos,
                                                     __half* __restrict__ out2h,
                                                     __half* __restrict__ outh) {
    int row = blockIdx.x;
    int t   = threadIdx.x;
    size_t off = (size_t)row * D_ + t;
    float v = a[off] + b[off];
    float mean = blockReduceSum(v) * (1.f / D_);
    float c = v - mean;
    float var = blockReduceSum(c * c) * (1.f / D_);
    float r = c * rsqrtf(var + 1e-5f) * gain[t] + beta[t];
    out[off] = r;
    if (out2h) out2h[off] = __float2half_rn(r + pos[off]);
    if (outh)  outh[off]  = __float2half_rn(r);
}

// ---------------- fp16 tensor-core GEMM, cp.async 2-stage, 128x128x32 ----------------
constexpr int GBM = 128, GBN = 128, GBK = 32;   // GBK in halves
constexpr int GLDH = 40;                        // half stride (20 words; conflict-free)
constexpr int GEMM_SMEM = 2 * (GBM + GBN) * GLDH * 2;   // 40960 B

template<bool RELU, bool MASK, typename CT>
__global__ __launch_bounds__(256, 3) void gemm_f16(const __half* __restrict__ A,
                                                   const __half* __restrict__ W,
                                                   const float* __restrict__ bias,
                                                   CT* __restrict__ C,
                                                   int M, int N, int K,
                                                   const unsigned char* __restrict__ mask) {
    extern __shared__ __half smh[];
    __half* Asm = smh;
    __half* Wsm = smh + 2 * GBM * GLDH;

    const int tid  = threadIdx.x;
    const int lane = tid & 31;
    const int wid  = tid >> 5;
    const int g    = lane >> 2;
    const int tig  = lane & 3;
    const int m0   = (wid & 1) * 64;
    const int n0   = (wid >> 1) * 32;
    const int bm   = blockIdx.y * GBM;
    const int bn   = blockIdx.x * GBN;

    const int lrow = tid >> 1;
    const int lcol = (tid & 1) * 16;

    const bool va = (bm + lrow) < M;
    const bool vw = (bn + lrow) < N;
    const __half* pA = A + (size_t)(bm + lrow) * K + lcol;
    const __half* pW = W + (size_t)(bn + lrow) * K + lcol;

    uint32_t aDst[2], wDst[2];
    #pragma unroll
    for (int b2 = 0; b2 < 2; b2++) {
        aDst[b2] = smem_u32(&Asm[b2 * GBM * GLDH + lrow * GLDH + lcol]);
        wDst[b2] = smem_u32(&Wsm[b2 * GBN * GLDH + lrow * GLDH + lcol]);
    }

    auto LOADcp = [&](int k0, int buf) {
        #pragma unroll
        for (int i = 0; i < 2; i++)
            cp16(aDst[buf] + i * 16, pA + k0 + i * 8, va ? 16 : 0);
        #pragma unroll
        for (int i = 0; i < 2; i++)
            cp16(wDst[buf] + i * 16, pW + k0 + i * 8, vw ? 16 : 0);
    };

    float acc[4][4][4] = {};

    auto COMPUTE = [&](int buf) {
        const __half* Ab = &Asm[buf * GBM * GLDH];
        const __half* Wb = &Wsm[buf * GBN * GLDH];
        #pragma unroll
        for (int kk = 0; kk < GBK; kk += 16) {
            uint32_t af[4][4], bf[4][2];
            #pragma unroll
            for (int am = 0; am < 4; am++) {
                const __half* p = &Ab[(m0 + am * 16 + g) * GLDH + kk + 2 * tig];
                af[am][0] = *(const uint32_t*)(p);
                af[am][1] = *(const uint32_t*)(p + 8 * GLDH);
                af[am][2] = *(const uint32_t*)(p + 8);
                af[am][3] = *(const uint32_t*)(p + 8 * GLDH + 8);
            }
            #pragma unroll
            for (int an = 0; an < 4; an++) {
                const __half* p = &Wb[(n0 + an * 8 + g) * GLDH + kk + 2 * tig];
                bf[an][0] = *(const uint32_t*)(p);
                bf[an][1] = *(const uint32_t*)(p + 8);
            }
            #pragma unroll
            for (int am = 0; am < 4; am++)
                #pragma unroll
                for (int an = 0; an < 4; an++)
                    MMA16(acc[am][an], af[am], bf[an]);
        }
    };

    const int nk = K / GBK;
    LOADcp(0, 0);
    CP_COMMIT();
    for (int t = 0; t < nk; t++) {
        cp_wait<0>();
        __syncthreads();
        if (t + 1 < nk) {
            LOADcp((t + 1) * GBK, (t + 1) & 1);
            CP_COMMIT();
        }
        COMPUTE(t & 1);
    }

    #pragma unroll
    for (int am = 0; am < 4; am++) {
        #pragma unroll
        for (int half_ = 0; half_ < 2; half_++) {
            int r = bm + m0 + am * 16 + g + half_ * 8;
            if (r >= M) continue;
            bool mz = false;
            if (MASK) mz = mask[(size_t)(r % B_) * S_ + (r / B_)] != 0;
            #pragma unroll
            for (int an = 0; an < 4; an++) {
                int c = bn + n0 + an * 8 + 2 * tig;
                if (c >= N) continue;
                float u0 = acc[am][an][half_ * 2 + 0] + bias[c];
                float u1 = acc[am][an][half_ * 2 + 1] + bias[c + 1];
                if (RELU) { u0 = fmaxf(u0, 0.f); u1 = fmaxf(u1, 0.f); }
                if (MASK && mz) { u0 = 0.f; u1 = 0.f; }
                if constexpr (sizeof(CT) == 2) {
                    *(__half2*)&C[(size_t)r * N + c] =
                        __halves2half2(__float2half_rn(u0), __float2half_rn(u1));
                } else {
                    *(float2*)&C[(size_t)r * N + c] = make_float2(u0, u1);
                }
            }
        }
    }
}

// ---------------- flash-style MHA, fully fp16 MMA ----------------
constexpr int FATT_SMEM = 18176 * 2 + (512 + 64) * 4;   // 38656 B

__global__ __launch_bounds__(256) void flash_attn_kernel(const __half* __restrict__ QK,
                                                         const __half* __restrict__ V,
                                                         __half* __restrict__ O) {
    extern __shared__ __half smh[];
    __half* Ks  = smh;            // 128 x 40
    __half* Vst = smh + 5120;     // 32 x 136
    __half* Ps  = smh + 9472;     // 64 x 136
    float*  rs  = (float*)(smh + 18176);
    float*  ls  = rs + 512;

    const int tid  = threadIdx.x;
    const int lane = tid & 31;
    const int wid  = tid >> 5;
    const int g    = lane >> 2;
    const int tig  = lane & 3;
    const int wm   = wid >> 2;
    const int wn   = wid & 3;
    const int m0w  = wm * 32;
    const int b    = blockIdx.y >> 3;
    const int h    = blockIdx.y & 7;
    const int q0   = blockIdx.x * 64;

    if (tid < 64) ls[tid] = 0.f;

    {
        const float scale = 0.1767766952966369f;
        int r = tid >> 2, c = (tid & 3) * 8;
        int q = q0 + r;
        __half* dst = Ps + r * 40 + c;
        if (q < NQ_) {
            const __half* src = QK + ((size_t)(q * B_ + b)) * SQK + h * DH_ + c;
            #pragma unroll
            for (int i = 0; i < 8; i++)
                dst[i] = __float2half_rn(__half2float(src[i]) * scale);
        } else {
            #pragma unroll
            for (int i = 0; i < 8; i++) dst[i] = __float2half_rn(0.f);
        }
    }
    __syncthreads();

    uint32_t aq[2][2][4];
    #pragma unroll
    for (int am = 0; am < 2; am++)
        #pragma unroll
        for (int ks2 = 0; ks2 < 2; ks2++) {
            const __half* p = Ps + (m0w + am * 16 + g) * 40 + ks2 * 16 + 2 * tig;
            aq[am][ks2][0] = *(const uint32_t*)(p);
            aq[am][ks2][1] = *(const uint32_t*)(p + 8 * 40);
            aq[am][ks2][2] = *(const uint32_t*)(p + 8);
            aq[am][ks2][3] = *(const uint32_t*)(p + 8 * 40 + 8);
        }

    float o[2][4][4] = {};

    const int kvr = tid >> 1;
    const int kvc = (tid & 1) * 16;
    uint32_t ksDst = smem_u32(&Ks[kvr * 40 + kvc]);

    for (int kt = 0; kt < 8; kt++) {
        __syncthreads();
        if (kt > 0 && tid < 64) {
            const float* r = rs + ((kt - 1) & 1) * 256;
            ls[tid] += r[tid] + r[64 + tid] + r[128 + tid] + r[192 + tid];
        }
        {
            int j = kt * 128 + kvr;
            bool vj = j < NQ_;
            const __half* srcK = QK + ((size_t)(j * B_ + b)) * SQK + 256 + h * DH_ + kvc;
            cp16(ksDst,      srcK,     vj ? 16 : 0);
            cp16(ksDst + 16, srcK + 8, vj ? 16 : 0);
            CP_COMMIT();
            const __half* srcV = V + ((size_t)(j * B_ + b)) * D_ + h * DH_ + kvc;
            #pragma unroll
            for (int i = 0; i < 8; i++) {
                __half2 hv = vj ? *(const __half2*)(srcV + 2 * i)
                                : __halves2half2(__float2half_rn(0.f), __float2half_rn(0.f));
                Vst[(kvc + 2 * i + 0) * 136 + kvr] = __low2half(hv);
                Vst[(kvc + 2 * i + 1) * 136 + kvr] = __high2half(hv);
            }
        }
        cp_wait<0>();
        __syncthreads();

        float s[2][4][4] = {};
        #pragma unroll
        for (int ks2 = 0; ks2 < 2; ks2++) {
            uint32_t bf[4][2];
            #pragma unroll
            for (int an = 0; an < 4; an++) {
                const __half* p = Ks + (wn * 32 + an * 8 + g) * 40 + ks2 * 16 + 2 * tig;
                bf[an][0] = *(const uint32_t*)(p);
                bf[an][1] = *(const uint32_t*)(p + 8);
            }
            #pragma unroll
            for (int am = 0; am < 2; am++)
                #pragma unroll
                for (int an = 0; an < 4; an++)
                    MMA16(s[am][an], aq[am][ks2], bf[an]);
        }

        float rp[2][2] = {{0.f, 0.f}, {0.f, 0.f}};
        #pragma unroll
        for (int am = 0; am < 2; am++) {
            int r0 = m0w + am * 16 + g;
            #pragma unroll
            for (int an = 0; an < 4; an++) {
                int cloc  = wn * 32 + an * 8 + 2 * tig;
                int cglob = kt * 128 + cloc;
                bool v0 = cglob < NQ_, v1 = (cglob + 1) < NQ_;
                float p0 = v0 ? __expf(s[am][an][0]) : 0.f;
                float p1 = v1 ? __expf(s[am][an][1]) : 0.f;
                float p2 = v0 ? __expf(s[am][an][2]) : 0.f;
                float p3 = v1 ? __expf(s[am][an][3]) : 0.f;
                rp[am][0] += p0 + p1;
                rp[am][1] += p2 + p3;
                *(__half2*)&Ps[r0 * 136 + cloc] =
                    __halves2half2(__float2half_rn(p0), __float2half_rn(p1));
                *(__half2*)&Ps[(r0 + 8) * 136 + cloc] =
                    __halves2half2(__float2half_rn(p2), __float2half_rn(p3));
            }
        }
        #pragma unroll
        for (int am = 0; am < 2; am++)
            #pragma unroll
            for (int hf = 0; hf < 2; hf++) {
                float v = rp[am][hf];
                v += __shfl_xor_sync(0xffffffffu, v, 1);
                v += __shfl_xor_sync(0xffffffffu, v, 2);
                rp[am][hf] = v;
            }
        if (tig == 0) {
            #pragma unroll
            for (int am = 0; am < 2; am++)
                #pragma unroll
                for (int hf = 0; hf < 2; hf++)
                    rs[(kt & 1) * 256 + wn * 64 + m0w + am * 16 + hf * 8 + g] = rp[am][hf];
        }
        __syncwarp();

        #pragma unroll
        for (int ks2 = 0; ks2 < 2; ks2++) {
            int kk = wn * 32 + ks2 * 16;
            uint32_t bf[4][2], af[2][4];
            #pragma unroll
            for (int an = 0; an < 4; an++) {
                const __half* p = Vst + (an * 8 + g) * 136 + kk + 2 * tig;
                bf[an][0] = *(const uint32_t*)(p);
                bf[an][1] = *(const uint32_t*)(p + 8);
            }
            #pragma unroll
            for (int am = 0; am < 2; am++) {
                const __half* p = Ps + (m0w + am * 16 + g) * 136 + kk + 2 * tig;
                af[am][0] = *(const uint32_t*)(p);
                af[am][1] = *(const uint32_t*)(p + 8 * 136);
                af[am][2] = *(const uint32_t*)(p + 8);
                af[am][3] = *(const uint32_t*)(p + 8 * 136 + 8);
            }
            #pragma unroll
            for (int am = 0; am < 2; am++)
                #pragma unroll
                for (int an = 0; an < 4; an++)
                    MMA16(o[am][an], af[am], bf[an]);
        }
    }

    __syncthreads();
    if (tid < 64) {
        const float* r = rs + 256;
        ls[tid] += r[tid] + r[64 + tid] + r[128 + tid] + r[192 + tid];
    }
    float* Obuf = (float*)smh;
    {
        float* Ob = Obuf + wn * (64 * 33);
        #pragma unroll
        for (int am = 0; am < 2; am++)
            #pragma unroll
            for (int an = 0; an < 4; an++) {
                int r0 = m0w + am * 16 + g;
                int c  = an * 8 + 2 * tig;
                Ob[r0 * 33 + c]           = o[am][an][0];
                Ob[r0 * 33 + c + 1]       = o[am][an][1];
                Ob[(r0 + 8) * 33 + c]     = o[am][an][2];
                Ob[(r0 + 8) * 33 + c + 1] = o[am][an][3];
            }
    }
    __syncthreads();
    for (int i = tid; i < 64 * 32; i += 256) {
        int r = i >> 5, d = i & 31;
        int q = q0 + r;
        if (q < NQ_) {
            float num = Obuf[r * 33 + d] + Obuf[2112 + r * 33 + d]
                      + Obuf[4224 + r * 33 + d] + Obuf[6336 + r * 33 + d];
            O[((size_t)(q * B_ + b)) * D_ + h * DH_ + d] = __float2half_rn(num / ls[r]);
        }
    }
}

// ---------------- deformable sampling (half value, half out; packed OAW) ----------------
__global__ __launch_bounds__(256) void deform_sample_kernel(const __half* __restrict__ VAL,
                                                            const float* __restrict__ OAW,
                                                            const float* __restrict__ REF,
                                                            __half* __restrict__ OUT) {
    int row = blockIdx.x;      // q*B + b
    int b = row % B_;
    int t = threadIdx.x;
    int h = t >> 5;
    int d = t & 31;

    const float* awp = OAW + (size_t)row * NOAW + 256 + h * 16;
    float w[16];
    float m = -1e30f;
    #pragma unroll
    for (int i = 0; i < 16; i++) { w[i] = awp[i]; m = fmaxf(m, w[i]); }
    float s = 0.f;
    #pragma unroll
    for (int i = 0; i < 16; i++) { w[i] = expf(w[i] - m); s += w[i]; }
    float inv = 1.f / s;

    const float* rp = REF + (size_t)row * 4;
    float rx = rp[0], ry = rp[1], rw = rp[2], rh = rp[3];
    const float* op = OAW + (size_t)row * NOAW + h * 32;

    const int LH[4] = {96, 48, 24, 12};
    const int LW[4] = {96, 48, 24, 12};
    const int LS[4] = {0, 9216, 11520, 12096};

    float acc = 0.f;
    #pragma unroll
    for (int lvl = 0; lvl < L_; lvl++) {
        int hh = LH[lvl], ww = LW[lvl], st = LS[lvl];
        #pragma unroll
        for (int p = 0; p < P_; p++) {
            float ox = op[lvl * 8 + p * 2 + 0];
            float oy = op[lvl * 8 + p * 2 + 1];
            float lx = rx + ox * (1.f / P_) * rw * 0.5f;
            float ly = ry + oy * (1.f / P_) * rh * 0.5f;
            float x = lx * ww - 0.5f;
            float y = ly * hh - 0.5f;
            float xf = floorf(x), yf = floorf(y);
            float fx = x - xf, fy = y - yf;
            int x0 = (int)xf, y0 = (int)yf;
            float aw = w[lvl * 4 + p] * inv;

            float c00 = (1.f - fx) * (1.f - fy) * aw;
            float c10 = fx * (1.f - fy) * aw;
            float c01 = (1.f - fx) * fy * aw;
            float c11 = fx * fy * aw;

            #pragma unroll
            for (int corner = 0; corner < 4; corner++) {
                int xi = x0 + (corner & 1);
                int yi = y0 + (corner >> 1);
                float wt = (corner == 0) ? c00 : (corner == 1) ? c10 : (corner == 2) ? c01 : c11;
                if (xi >= 0 && xi < ww && yi >= 0 && yi < hh && wt != 0.f) {
                    acc += wt * __half2float(
                        VAL[((size_t)(st + yi * ww + xi) * B_ + b) * D_ + h * DH_ + d]);
                }
            }
        }
    }
    OUT[(size_t)row * D_ + h * DH_ + d] = __float2half_rn(acc);
}

// ---------------- launch ----------------
template<typename T>
static T* symT(const void* s) {
    void* p = nullptr;
    cudaGetSymbolAddress(&p, s);
    return (T*)p;
}

extern "C" void kernel_launch(void* const* d_in, const int* in_sizes, int n_in,
                              void* d_out, int out_size) {
    const float* queries = (const float*)d_in[0];
    const float* pos     = (const float*)d_in[1];
    const float* refpts  = (const float*)d_in[2];
    const float* memory  = (const float*)d_in[3];
    const unsigned char* mask = (const unsigned char*)d_in[4];
    const float* in_w    = (const float*)d_in[7];
    const float* in_b    = (const float*)d_in[8];
    const float* out_w   = (const float*)d_in[9];
    const float* out_b   = (const float*)d_in[10];
    const float* n1g     = (const float*)d_in[11];
    const float* n1b     = (const float*)d_in[12];
    const float* n2g     = (const float*)d_in[13];
    const float* n2b     = (const float*)d_in[14];
    const float* n3g     = (const float*)d_in[15];
    const float* n3b     = (const float*)d_in[16];
    const float* l1w     = (const float*)d_in[17];
    const float* l1b     = (const float*)d_in[18];
    const float* l2w     = (const float*)d_in[19];
    const float* l2b     = (const float*)d_in[20];
    const float* off_w   = (const float*)d_in[21];
    const float* off_b   = (const float*)d_in[22];
    const float* aw_w    = (const float*)d_in[23];
    const float* aw_b    = (const float*)d_in[24];
    const float* val_w   = (const float*)d_in[25];
    const float* val_b   = (const float*)d_in[26];
    const float* cout_w  = (const float*)d_in[27];
    const float* cout_b  = (const float*)d_in[28];

    float*  SA    = symT<float>(g_SA);
    float*  X1    = symT<float>(g_X1);
    float*  OAW   = symT<float>(g_OAW);
    float*  CA    = symT<float>(g_CA);
    float*  X2    = symT<float>(g_X2);
    float*  FF    = symT<float>(g_FF);
    float*  oab   = symT<float>(g_oab);
    __half* ADDQh = symT<__half>(g_ADDQh);
    __half* Qh    = symT<__half>(g_Qh);
    __half* MEMh  = symT<__half>(g_MEMh);
    __half* QKph  = symT<__half>(g_QKph);
    __half* Vh    = symT<__half>(g_Vh);
    __half* SAph  = symT<__half>(g_SAph);
    __half* QINh  = symT<__half>(g_QINh);
    __half* VALh  = symT<__half>(g_VALh);
    __half* DOUTh = symT<__half>(g_DOUTh);
    __half* X2h   = symT<__half>(g_X2h);
    __half* HHh   = symT<__half>(g_HHh);
    __half* inwh  = symT<__half>(g_inwh);
    __half* outwh = symT<__half>(g_outwh);
    __half* valwh = symT<__half>(g_valwh);
    __half* oawh  = symT<__half>(g_oawh);
    __half* cowh  = symT<__half>(g_cowh);
    __half* l1wh  = symT<__half>(g_l1wh);
    __half* l2wh  = symT<__half>(g_l2wh);

    cudaFuncSetAttribute(flash_attn_kernel, cudaFuncAttributeMaxDynamicSharedMemorySize, FATT_SMEM);

    static cudaStream_t s2 = nullptr, s3 = nullptr;
    static cudaEvent_t  eFork = nullptr, eJoin = nullptr, eA = nullptr, eV = nullptr;
    if (s2 == nullptr) {
        cudaStreamCreate(&s2);
        cudaStreamCreate(&s3);
        cudaEventCreateWithFlags(&eFork, cudaEventDisableTiming);
        cudaEventCreateWithFlags(&eJoin, cudaEventDisableTiming);
        cudaEventCreateWithFlags(&eA,    cudaEventDisableTiming);
        cudaEventCreateWithFlags(&eV,    cudaEventDisableTiming);
    }

    const int nElem = NR_ * D_;
    dim3 gQK(SQK / GBN, (NR_ + GBM - 1) / GBM);   // (4, 57)
    dim3 gP (D_ / GBN,  (NR_ + GBM - 1) / GBM);   // (2, 57)

    // ---- fork: s2 = post-attention weights + value branch ----
    cudaEventRecord(eFork, 0);
    cudaStreamWaitEvent(s2, eFork, 0);

    cvt_multi<<<512, 256, 0, s2>>>(out_w, outwh, D_ * D_, cout_w, cowh, D_ * D_,
                                   l1w, l1wh, DFF_ * D_, l2w, l2wh, D_ * DFF_);
    cvt_multi<<<2048, 256, 0, s2>>>(off_w, oawh, 256 * D_, aw_w, oawh + 256 * D_, 128 * D_,
                                    val_w, valwh, D_ * D_, memory, MEMh, S_ * B_ * D_);
    pack_bias<<<1, 384, 0, s2>>>(off_b, aw_b, oab);
    dim3 gV(D_ / GBN, (S_ * B_) / GBM);           // (2, 765)
    gemm_f16<false, true, __half><<<gV, 256, GEMM_SMEM, s2>>>(MEMh, valwh, val_b, VALh, S_ * B_, D_, D_, mask);
    cudaEventRecord(eJoin, s2);

    // ---- main stream: self-attention chain ----
    cvt_multi<<<256, 256>>>(in_w, inwh, 3 * D_ * D_, nullptr, nullptr, 0,
                            nullptr, nullptr, 0, nullptr, nullptr, 0);
    add2q_kernel<<<NR_, 256>>>(queries, pos, ADDQh, Qh, nElem);
    cudaEventRecord(eA, 0);

    // s3: V projection concurrent with QK projection
    cudaStreamWaitEvent(s3, eA, 0);
    gemm_f16<false, false, __half><<<gP, 256, GEMM_SMEM, s3>>>(Qh, inwh + 2 * D_ * D_, in_b + 2 * D_, Vh, NR_, D_, D_, nullptr);
    cudaEventRecord(eV, s3);

    gemm_f16<false, false, __half><<<gQK, 256, GEMM_SMEM>>>(ADDQh, inwh, in_b, QKph, NR_, SQK, D_, nullptr);
    cudaStreamWaitEvent(0, eV, 0);

    dim3 gFA((NQ_ + 63) / 64, B_ * H_);           // (15, 64)
    flash_attn_kernel<<<gFA, 256, FATT_SMEM>>>(QKph, Vh, SAph);

    cudaStreamWaitEvent(0, eJoin, 0);

    gemm_f16<false, false, float><<<gP, 256, GEMM_SMEM>>>(SAph, outwh, out_b, SA, NR_, D_, D_, nullptr);

    add_ln_kernel<<<NR_, 256>>>(queries, SA, n2g, n2b, X1, pos, QINh, nullptr);

    dim3 gOA((NOAW + GBN - 1) / GBN, (NR_ + GBM - 1) / GBM);   // (3, 57)
    gemm_f16<false, false, float><<<gOA, 256, GEMM_SMEM>>>(QINh, oawh, oab, OAW, NR_, NOAW, D_, nullptr);

    deform_sample_kernel<<<NR_, 256>>>(VALh, OAW, refpts, DOUTh);

    gemm_f16<false, false, float><<<gP, 256, GEMM_SMEM>>>(DOUTh, cowh, cout_b, CA, NR_, D_, D_, nullptr);

    add_ln_kernel<<<NR_, 256>>>(X1, CA, n1g, n1b, X2, nullptr, nullptr, X2h);

    dim3 gF1(DFF_ / GBN, (NR_ + GBM - 1) / GBM);  // (16, 57)
    gemm_f16<true, false, __half><<<gF1, 256, GEMM_SMEM>>>(X2h, l1wh, l1b, HHh, NR_, DFF_, D_, nullptr);
    gemm_f16<false, false, float><<<gP, 256, GEMM_SMEM>>>(HHh, l2wh, l2b, FF, NR_, D_, DFF_, nullptr);

    add_ln_kernel<<<NR_, 256>>>(X2, FF, n3g, n3b, (float*)d_out, nullptr, nullptr, nullptr);
}

// round 15
// speedup vs baseline: 1.0983x; 1.0983x over previous
#include <cuda_runtime.h>
#include <cuda_fp16.h>
#include <math.h>
#include <stdint.h>

// ---------------- constants ----------------
constexpr int D_   = 256;
constexpr int H_   = 8;
constexpr int L_   = 4;
constexpr int P_   = 4;
constexpr int DFF_ = 2048;
constexpr int DH_  = 32;
constexpr int NQ_  = 900;
constexpr int B_   = 8;
constexpr int S_   = 12240;
constexpr int NR_  = NQ_ * B_;          // 7200 rows
constexpr int SQK  = 512;               // row stride of fused Q|K projection buffer
constexpr int NOAW = 384;               // fused offs(256) + aw(128) projection width

// ---------------- scratch (no allocations allowed) ----------------
__device__ __align__(256) float  g_SA   [NR_ * D_];
__device__ __align__(256) float  g_X1   [NR_ * D_];
__device__ __align__(256) float  g_OAW  [NR_ * NOAW];
__device__ __align__(256) float  g_CA   [NR_ * D_];
__device__ __align__(256) float  g_X2   [NR_ * D_];
__device__ __align__(256) float  g_FF   [NR_ * D_];
__device__ __align__(256) float  g_oab  [NOAW];
__device__ __align__(256) __half g_ADDQh[NR_ * D_];
__device__ __align__(256) __half g_Qh   [NR_ * D_];
__device__ __align__(256) __half g_MEMh [S_ * B_ * D_];
__device__ __align__(256) __half g_QKph [NR_ * SQK];
__device__ __align__(256) __half g_Vh   [NR_ * D_];
__device__ __align__(256) __half g_SAph [NR_ * D_];
__device__ __align__(256) __half g_QINh [NR_ * D_];
__device__ __align__(256) __half g_VALh [S_ * B_ * D_];
__device__ __align__(256) __half g_DOUTh[NR_ * D_];
__device__ __align__(256) __half g_X2h  [NR_ * D_];
__device__ __align__(256) __half g_HHh  [NR_ * DFF_];
__device__ __align__(256) __half g_inwh [3 * D_ * D_];
__device__ __align__(256) __half g_outwh[D_ * D_];
__device__ __align__(256) __half g_valwh[D_ * D_];
__device__ __align__(256) __half g_oawh [NOAW * D_];
__device__ __align__(256) __half g_cowh [D_ * D_];
__device__ __align__(256) __half g_l1wh [DFF_ * D_];
__device__ __align__(256) __half g_l2wh [D_ * DFF_];

// ---------------- helpers ----------------
__device__ __forceinline__ float blockReduceSum(float v) {
    __shared__ float red[32];
    int lane = threadIdx.x & 31;
    int wid  = threadIdx.x >> 5;
    #pragma unroll
    for (int o = 16; o > 0; o >>= 1) v += __shfl_xor_sync(0xffffffffu, v, o);
    if (lane == 0) red[wid] = v;
    __syncthreads();
    float r = (threadIdx.x < (blockDim.x >> 5)) ? red[threadIdx.x] : 0.f;
    if (wid == 0) {
        #pragma unroll
        for (int o = 16; o > 0; o >>= 1) r += __shfl_xor_sync(0xffffffffu, r, o);
        if (lane == 0) red[0] = r;
    }
    __syncthreads();
    r = red[0];
    __syncthreads();
    return r;
}

__device__ __forceinline__ uint32_t smem_u32(const void* p) {
    return (uint32_t)__cvta_generic_to_shared(p);
}

__device__ __forceinline__ void cp16(uint32_t dst, const void* src, int srcBytes) {
    asm volatile("cp.async.cg.shared.global [%0], [%1], 16, %2;\n"
                 :: "r"(dst), "l"(src), "r"(srcBytes));
}
#define CP_COMMIT() asm volatile("cp.async.commit_group;\n" ::: "memory")
template<int N_>
__device__ __forceinline__ void cp_wait() {
    asm volatile("cp.async.wait_group %0;\n" :: "n"(N_) : "memory");
}

// fp16 MMA, fp32 accumulate
#define MMA16(d, a, b2) asm volatile( \
    "mma.sync.aligned.m16n8k16.row.col.f32.f16.f16.f32 " \
    "{%0,%1,%2,%3}, {%4,%5,%6,%7}, {%8,%9}, {%0,%1,%2,%3};\n" \
    : "+f"((d)[0]), "+f"((d)[1]), "+f"((d)[2]), "+f"((d)[3]) \
    : "r"((a)[0]), "r"((a)[1]), "r"((a)[2]), "r"((a)[3]), \
      "r"((b2)[0]), "r"((b2)[1]))

// ldmatrix x4 (b16): 4 8x8 matrices from per-lane-group row addresses
#define LDSM4(r0, r1, r2, r3, addr) asm volatile( \
    "ldmatrix.sync.aligned.m8n8.x4.shared.b16 {%0,%1,%2,%3}, [%4];" \
    : "=r"(r0), "=r"(r1), "=r"(r2), "=r"(r3) : "r"(addr))

// ---------------- f32 -> f16 batch convert ----------------
__global__ __launch_bounds__(256) void cvt_multi(const float* a0, __half* o0, int n0,
                                                 const float* a1, __half* o1, int n1,
                                                 const float* a2, __half* o2, int n2,
                                                 const float* a3, __half* o3, int n3) {
    int stride = gridDim.x * 256;
    int base = blockIdx.x * 256 + threadIdx.x;
    for (int i = base; i < n0; i += stride) o0[i] = __float2half_rn(a0[i]);
    for (int i = base; i < n1; i += stride) o1[i] = __float2half_rn(a1[i]);
    for (int i = base; i < n2; i += stride) o2[i] = __float2half_rn(a2[i]);
    for (int i = base; i < n3; i += stride) o3[i] = __float2half_rn(a3[i]);
}

__global__ __launch_bounds__(384) void pack_bias(const float* __restrict__ ob,
                                                 const float* __restrict__ ab,
                                                 float* __restrict__ dst) {
    int i = threadIdx.x;
    dst[i] = (i < 256) ? ob[i] : ab[i - 256];
}

__global__ __launch_bounds__(256) void add2q_kernel(const float* __restrict__ q,
                                                    const float* __restrict__ pos,
                                                    __half* __restrict__ addq,
                                                    __half* __restrict__ qh, int n) {
    int i = blockIdx.x * 256 + threadIdx.x;
    if (i < n) {
        float a = q[i];
        addq[i] = __float2half_rn(a + pos[i]);
        qh[i]   = __float2half_rn(a);
    }
}

__global__ __launch_bounds__(256) void add_ln_kernel(const float* __restrict__ a,
                                                     const float* __restrict__ b,
                                                     const float* __restrict__ gain,
                                                     const float* __restrict__ beta,
                                                     float* __restrict__ out,
                                                     const float* __restrict__ pos,
                                                     __half* __restrict__ out2h,
                                                     __half* __restrict__ outh) {
    int row = blockIdx.x;
    int t   = threadIdx.x;
    size_t off = (size_t)row * D_ + t;
    float v = a[off] + b[off];
    float mean = blockReduceSum(v) * (1.f / D_);
    float c = v - mean;
    float var = blockReduceSum(c * c) * (1.f / D_);
    float r = c * rsqrtf(var + 1e-5f) * gain[t] + beta[t];
    out[off] = r;
    if (out2h) out2h[off] = __float2half_rn(r + pos[off]);
    if (outh)  outh[off]  = __float2half_rn(r);
}

// ---------------- fp16 tensor-core GEMM, cp.async 2-stage, 128x128x32, ldmatrix ------
constexpr int GBM = 128, GBN = 128, GBK = 32;   // GBK in halves
constexpr int GLDH = 40;                        // half stride (20 words; conflict-free)
constexpr int GEMM_SMEM = 2 * (GBM + GBN) * GLDH * 2;   // 40960 B

template<bool RELU, bool MASK, typename CT>
__global__ __launch_bounds__(256) void gemm_f16(const __half* __restrict__ A,
                                                const __half* __restrict__ W,
                                                const float* __restrict__ bias,
                                                CT* __restrict__ C,
                                                int M, int N, int K,
                                                const unsigned char* __restrict__ mask) {
    extern __shared__ __half smh[];
    __half* Asm = smh;
    __half* Wsm = smh + 2 * GBM * GLDH;

    const int tid  = threadIdx.x;
    const int lane = tid & 31;
    const int wid  = tid >> 5;
    const int g    = lane >> 2;
    const int tig  = lane & 3;
    const int quad = lane >> 3;      // 0..3 (ldmatrix lane group)
    const int r8   = lane & 7;
    const int m0   = (wid & 1) * 64;
    const int n0   = (wid >> 1) * 32;
    const int bm   = blockIdx.y * GBM;
    const int bn   = blockIdx.x * GBN;

    const int lrow = tid >> 1;
    const int lcol = (tid & 1) * 16;

    const bool va = (bm + lrow) < M;
    const bool vw = (bn + lrow) < N;
    const __half* pA = A + (size_t)(bm + lrow) * K + lcol;
    const __half* pW = W + (size_t)(bn + lrow) * K + lcol;

    uint32_t aDst[2], wDst[2];
    #pragma unroll
    for (int b2 = 0; b2 < 2; b2++) {
        aDst[b2] = smem_u32(&Asm[b2 * GBM * GLDH + lrow * GLDH + lcol]);
        wDst[b2] = smem_u32(&Wsm[b2 * GBN * GLDH + lrow * GLDH + lcol]);
    }

    auto LOADcp = [&](int k0, int buf) {
        #pragma unroll
        for (int i = 0; i < 2; i++)
            cp16(aDst[buf] + i * 16, pA + k0 + i * 8, va ? 16 : 0);
        #pragma unroll
        for (int i = 0; i < 2; i++)
            cp16(wDst[buf] + i * 16, pW + k0 + i * 8, vw ? 16 : 0);
    };

    float acc[4][4][4] = {};

    auto COMPUTE = [&](int buf) {
        const __half* Ab = &Asm[buf * GBM * GLDH];
        const __half* Wb = &Wsm[buf * GBN * GLDH];
        #pragma unroll
        for (int kk = 0; kk < GBK; kk += 16) {
            uint32_t af[4][4], bf[4][2];
            // A fragments: 4x ldmatrix.x4
            // lane groups -> matrices: 0: rows m..m+7/k, 1: rows m+8../k, 2: rows m../k+8, 3: rows m+8../k+8
            #pragma unroll
            for (int am = 0; am < 4; am++) {
                const __half* p = &Ab[(m0 + am * 16 + (quad & 1) * 8 + r8) * GLDH
                                      + kk + (quad >> 1) * 8];
                LDSM4(af[am][0], af[am][1], af[am][2], af[am][3], smem_u32(p));
            }
            // B fragments: 2x ldmatrix.x4 (each covers an, an+1)
            // groups: 0 -> bf[an][0], 1 -> bf[an][1], 2 -> bf[an+1][0], 3 -> bf[an+1][1]
            #pragma unroll
            for (int anp = 0; anp < 2; anp++) {
                const __half* p = &Wb[(n0 + anp * 16 + (quad >> 1) * 8 + r8) * GLDH
                                      + kk + (quad & 1) * 8];
                LDSM4(bf[2 * anp][0], bf[2 * anp][1], bf[2 * anp + 1][0], bf[2 * anp + 1][1],
                      smem_u32(p));
            }
            #pragma unroll
            for (int am = 0; am < 4; am++)
                #pragma unroll
                for (int an = 0; an < 4; an++)
                    MMA16(acc[am][an], af[am], bf[an]);
        }
    };

    const int nk = K / GBK;
    LOADcp(0, 0);
    CP_COMMIT();
    for (int t = 0; t < nk; t++) {
        cp_wait<0>();
        __syncthreads();
        if (t + 1 < nk) {
            LOADcp((t + 1) * GBK, (t + 1) & 1);
            CP_COMMIT();
        }
        COMPUTE(t & 1);
    }

    #pragma unroll
    for (int am = 0; am < 4; am++) {
        #pragma unroll
        for (int half_ = 0; half_ < 2; half_++) {
            int r = bm + m0 + am * 16 + g + half_ * 8;
            if (r >= M) continue;
            bool mz = false;
            if (MASK) mz = mask[(size_t)(r % B_) * S_ + (r / B_)] != 0;
            #pragma unroll
            for (int an = 0; an < 4; an++) {
                int c = bn + n0 + an * 8 + 2 * tig;
                if (c >= N) continue;
                float u0 = acc[am][an][half_ * 2 + 0] + bias[c];
                float u1 = acc[am][an][half_ * 2 + 1] + bias[c + 1];
                if (RELU) { u0 = fmaxf(u0, 0.f); u1 = fmaxf(u1, 0.f); }
                if (MASK && mz) { u0 = 0.f; u1 = 0.f; }
                if constexpr (sizeof(CT) == 2) {
                    *(__half2*)&C[(size_t)r * N + c] =
                        __halves2half2(__float2half_rn(u0), __float2half_rn(u1));
                } else {
                    *(float2*)&C[(size_t)r * N + c] = make_float2(u0, u1);
                }
            }
        }
    }
}

// ---------------- flash-style MHA, fully fp16 MMA ----------------
constexpr int FATT_SMEM = 18176 * 2 + (512 + 64) * 4;   // 38656 B

__global__ __launch_bounds__(256) void flash_attn_kernel(const __half* __restrict__ QK,
                                                         const __half* __restrict__ V,
                                                         __half* __restrict__ O) {
    extern __shared__ __half smh[];
    __half* Ks  = smh;            // 128 x 40
    __half* Vst = smh + 5120;     // 32 x 136
    __half* Ps  = smh + 9472;     // 64 x 136
    float*  rs  = (float*)(smh + 18176);
    float*  ls  = rs + 512;

    const int tid  = threadIdx.x;
    const int lane = tid & 31;
    const int wid  = tid >> 5;
    const int g    = lane >> 2;
    const int tig  = lane & 3;
    const int wm   = wid >> 2;
    const int wn   = wid & 3;
    const int m0w  = wm * 32;
    const int b    = blockIdx.y >> 3;
    const int h    = blockIdx.y & 7;
    const int q0   = blockIdx.x * 64;

    if (tid < 64) ls[tid] = 0.f;

    {
        const float scale = 0.1767766952966369f;
        int r = tid >> 2, c = (tid & 3) * 8;
        int q = q0 + r;
        __half* dst = Ps + r * 40 + c;
        if (q < NQ_) {
            const __half* src = QK + ((size_t)(q * B_ + b)) * SQK + h * DH_ + c;
            #pragma unroll
            for (int i = 0; i < 8; i++)
                dst[i] = __float2half_rn(__half2float(src[i]) * scale);
        } else {
            #pragma unroll
            for (int i = 0; i < 8; i++) dst[i] = __float2half_rn(0.f);
        }
    }
    __syncthreads();

    uint32_t aq[2][2][4];
    #pragma unroll
    for (int am = 0; am < 2; am++)
        #pragma unroll
        for (int ks2 = 0; ks2 < 2; ks2++) {
            const __half* p = Ps + (m0w + am * 16 + g) * 40 + ks2 * 16 + 2 * tig;
            aq[am][ks2][0] = *(const uint32_t*)(p);
            aq[am][ks2][1] = *(const uint32_t*)(p + 8 * 40);
            aq[am][ks2][2] = *(const uint32_t*)(p + 8);
            aq[am][ks2][3] = *(const uint32_t*)(p + 8 * 40 + 8);
        }

    float o[2][4][4] = {};

    const int kvr = tid >> 1;
    const int kvc = (tid & 1) * 16;
    uint32_t ksDst = smem_u32(&Ks[kvr * 40 + kvc]);

    for (int kt = 0; kt < 8; kt++) {
        __syncthreads();
        if (kt > 0 && tid < 64) {
            const float* r = rs + ((kt - 1) & 1) * 256;
            ls[tid] += r[tid] + r[64 + tid] + r[128 + tid] + r[192 + tid];
        }
        {
            int j = kt * 128 + kvr;
            bool vj = j < NQ_;
            const __half* srcK = QK + ((size_t)(j * B_ + b)) * SQK + 256 + h * DH_ + kvc;
            cp16(ksDst,      srcK,     vj ? 16 : 0);
            cp16(ksDst + 16, srcK + 8, vj ? 16 : 0);
            CP_COMMIT();
            const __half* srcV = V + ((size_t)(j * B_ + b)) * D_ + h * DH_ + kvc;
            #pragma unroll
            for (int i = 0; i < 8; i++) {
                __half2 hv = vj ? *(const __half2*)(srcV + 2 * i)
                                : __halves2half2(__float2half_rn(0.f), __float2half_rn(0.f));
                Vst[(kvc + 2 * i + 0) * 136 + kvr] = __low2half(hv);
                Vst[(kvc + 2 * i + 1) * 136 + kvr] = __high2half(hv);
            }
        }
        cp_wait<0>();
        __syncthreads();

        float s[2][4][4] = {};
        #pragma unroll
        for (int ks2 = 0; ks2 < 2; ks2++) {
            uint32_t bf[4][2];
            #pragma unroll
            for (int an = 0; an < 4; an++) {
                const __half* p = Ks + (wn * 32 + an * 8 + g) * 40 + ks2 * 16 + 2 * tig;
                bf[an][0] = *(const uint32_t*)(p);
                bf[an][1] = *(const uint32_t*)(p + 8);
            }
            #pragma unroll
            for (int am = 0; am < 2; am++)
                #pragma unroll
                for (int an = 0; an < 4; an++)
                    MMA16(s[am][an], aq[am][ks2], bf[an]);
        }

        float rp[2][2] = {{0.f, 0.f}, {0.f, 0.f}};
        #pragma unroll
        for (int am = 0; am < 2; am++) {
            int r0 = m0w + am * 16 + g;
            #pragma unroll
            for (int an = 0; an < 4; an++) {
                int cloc  = wn * 32 + an * 8 + 2 * tig;
                int cglob = kt * 128 + cloc;
                bool v0 = cglob < NQ_, v1 = (cglob + 1) < NQ_;
                float p0 = v0 ? __expf(s[am][an][0]) : 0.f;
                float p1 = v1 ? __expf(s[am][an][1]) : 0.f;
                float p2 = v0 ? __expf(s[am][an][2]) : 0.f;
                float p3 = v1 ? __expf(s[am][an][3]) : 0.f;
                rp[am][0] += p0 + p1;
                rp[am][1] += p2 + p3;
                *(__half2*)&Ps[r0 * 136 + cloc] =
                    __halves2half2(__float2half_rn(p0), __float2half_rn(p1));
                *(__half2*)&Ps[(r0 + 8) * 136 + cloc] =
                    __halves2half2(__float2half_rn(p2), __float2half_rn(p3));
            }
        }
        #pragma unroll
        for (int am = 0; am < 2; am++)
            #pragma unroll
            for (int hf = 0; hf < 2; hf++) {
                float v = rp[am][hf];
                v += __shfl_xor_sync(0xffffffffu, v, 1);
                v += __shfl_xor_sync(0xffffffffu, v, 2);
                rp[am][hf] = v;
            }
        if (tig == 0) {
            #pragma unroll
            for (int am = 0; am < 2; am++)
                #pragma unroll
                for (int hf = 0; hf < 2; hf++)
                    rs[(kt & 1) * 256 + wn * 64 + m0w + am * 16 + hf * 8 + g] = rp[am][hf];
        }
        __syncwarp();

        #pragma unroll
        for (int ks2 = 0; ks2 < 2; ks2++) {
            int kk = wn * 32 + ks2 * 16;
            uint32_t bf[4][2], af[2][4];
            #pragma unroll
            for (int an = 0; an < 4; an++) {
                const __half* p = Vst + (an * 8 + g) * 136 + kk + 2 * tig;
                bf[an][0] = *(const uint32_t*)(p);
                bf[an][1] = *(const uint32_t*)(p + 8);
            }
            #pragma unroll
            for (int am = 0; am < 2; am++) {
                const __half* p = Ps + (m0w + am * 16 + g) * 136 + kk + 2 * tig;
                af[am][0] = *(const uint32_t*)(p);
                af[am][1] = *(const uint32_t*)(p + 8 * 136);
                af[am][2] = *(const uint32_t*)(p + 8);
                af[am][3] = *(const uint32_t*)(p + 8 * 136 + 8);
            }
            #pragma unroll
            for (int am = 0; am < 2; am++)
                #pragma unroll
                for (int an = 0; an < 4; an++)
                    MMA16(o[am][an], af[am], bf[an]);
        }
    }

    __syncthreads();
    if (tid < 64) {
        const float* r = rs + 256;
        ls[tid] += r[tid] + r[64 + tid] + r[128 + tid] + r[192 + tid];
    }
    float* Obuf = (float*)smh;
    {
        float* Ob = Obuf + wn * (64 * 33);
        #pragma unroll
        for (int am = 0; am < 2; am++)
            #pragma unroll
            for (int an = 0; an < 4; an++) {
                int r0 = m0w + am * 16 + g;
                int c  = an * 8 + 2 * tig;
                Ob[r0 * 33 + c]           = o[am][an][0];
                Ob[r0 * 33 + c + 1]       = o[am][an][1];
                Ob[(r0 + 8) * 33 + c]     = o[am][an][2];
                Ob[(r0 + 8) * 33 + c + 1] = o[am][an][3];
            }
    }
    __syncthreads();
    for (int i = tid; i < 64 * 32; i += 256) {
        int r = i >> 5, d = i & 31;
        int q = q0 + r;
        if (q < NQ_) {
            float num = Obuf[r * 33 + d] + Obuf[2112 + r * 33 + d]
                      + Obuf[4224 + r * 33 + d] + Obuf[6336 + r * 33 + d];
            O[((size_t)(q * B_ + b)) * D_ + h * DH_ + d] = __float2half_rn(num / ls[r]);
        }
    }
}

// ---------------- deformable sampling (half value, half out; packed OAW) ----------------
__global__ __launch_bounds__(256) void deform_sample_kernel(const __half* __restrict__ VAL,
                                                            const float* __restrict__ OAW,
                                                            const float* __restrict__ REF,
                                                            __half* __restrict__ OUT) {
    int row = blockIdx.x;      // q*B + b
    int b = row % B_;
    int t = threadIdx.x;
    int h = t >> 5;
    int d = t & 31;

    const float* awp = OAW + (size_t)row * NOAW + 256 + h * 16;
    float w[16];
    float m = -1e30f;
    #pragma unroll
    for (int i = 0; i < 16; i++) { w[i] = awp[i]; m = fmaxf(m, w[i]); }
    float s = 0.f;
    #pragma unroll
    for (int i = 0; i < 16; i++) { w[i] = expf(w[i] - m); s += w[i]; }
    float inv = 1.f / s;

    const float* rp = REF + (size_t)row * 4;
    float rx = rp[0], ry = rp[1], rw = rp[2], rh = rp[3];
    const float* op = OAW + (size_t)row * NOAW + h * 32;

    const int LH[4] = {96, 48, 24, 12};
    const int LW[4] = {96, 48, 24, 12};
    const int LS[4] = {0, 9216, 11520, 12096};

    float acc = 0.f;
    #pragma unroll
    for (int lvl = 0; lvl < L_; lvl++) {
        int hh = LH[lvl], ww = LW[lvl], st = LS[lvl];
        #pragma unroll
        for (int p = 0; p < P_; p++) {
            float ox = op[lvl * 8 + p * 2 + 0];
            float oy = op[lvl * 8 + p * 2 + 1];
            float lx = rx + ox * (1.f / P_) * rw * 0.5f;
            float ly = ry + oy * (1.f / P_) * rh * 0.5f;
            float x = lx * ww - 0.5f;
            float y = ly * hh - 0.5f;
            float xf = floorf(x), yf = floorf(y);
            float fx = x - xf, fy = y - yf;
            int x0 = (int)xf, y0 = (int)yf;
            float aw = w[lvl * 4 + p] * inv;

            float c00 = (1.f - fx) * (1.f - fy) * aw;
            float c10 = fx * (1.f - fy) * aw;
            float c01 = (1.f - fx) * fy * aw;
            float c11 = fx * fy * aw;

            #pragma unroll
            for (int corner = 0; corner < 4; corner++) {
                int xi = x0 + (corner & 1);
                int yi = y0 + (corner >> 1);
                float wt = (corner == 0) ? c00 : (corner == 1) ? c10 : (corner == 2) ? c01 : c11;
                if (xi >= 0 && xi < ww && yi >= 0 && yi < hh && wt != 0.f) {
                    acc += wt * __half2float(
                        VAL[((size_t)(st + yi * ww + xi) * B_ + b) * D_ + h * DH_ + d]);
                }
            }
        }
    }
    OUT[(size_t)row * D_ + h * DH_ + d] = __float2half_rn(acc);
}

// ---------------- launch ----------------
template<typename T>
static T* symT(const void* s) {
    void* p = nullptr;
    cudaGetSymbolAddress(&p, s);
    return (T*)p;
}

extern "C" void kernel_launch(void* const* d_in, const int* in_sizes, int n_in,
                              void* d_out, int out_size) {
    const float* queries = (const float*)d_in[0];
    const float* pos     = (const float*)d_in[1];
    const float* refpts  = (const float*)d_in[2];
    const float* memory  = (const float*)d_in[3];
    const unsigned char* mask = (const unsigned char*)d_in[4];
    const float* in_w    = (const float*)d_in[7];
    const float* in_b    = (const float*)d_in[8];
    const float* out_w   = (const float*)d_in[9];
    const float* out_b   = (const float*)d_in[10];
    const float* n1g     = (const float*)d_in[11];
    const float* n1b     = (const float*)d_in[12];
    const float* n2g     = (const float*)d_in[13];
    const float* n2b     = (const float*)d_in[14];
    const float* n3g     = (const float*)d_in[15];
    const float* n3b     = (const float*)d_in[16];
    const float* l1w     = (const float*)d_in[17];
    const float* l1b     = (const float*)d_in[18];
    const float* l2w     = (const float*)d_in[19];
    const float* l2b     = (const float*)d_in[20];
    const float* off_w   = (const float*)d_in[21];
    const float* off_b   = (const float*)d_in[22];
    const float* aw_w    = (const float*)d_in[23];
    const float* aw_b    = (const float*)d_in[24];
    const float* val_w   = (const float*)d_in[25];
    const float* val_b   = (const float*)d_in[26];
    const float* cout_w  = (const float*)d_in[27];
    const float* cout_b  = (const float*)d_in[28];

    float*  SA    = symT<float>(g_SA);
    float*  X1    = symT<float>(g_X1);
    float*  OAW   = symT<float>(g_OAW);
    float*  CA    = symT<float>(g_CA);
    float*  X2    = symT<float>(g_X2);
    float*  FF    = symT<float>(g_FF);
    float*  oab   = symT<float>(g_oab);
    __half* ADDQh = symT<__half>(g_ADDQh);
    __half* Qh    = symT<__half>(g_Qh);
    __half* MEMh  = symT<__half>(g_MEMh);
    __half* QKph  = symT<__half>(g_QKph);
    __half* Vh    = symT<__half>(g_Vh);
    __half* SAph  = symT<__half>(g_SAph);
    __half* QINh  = symT<__half>(g_QINh);
    __half* VALh  = symT<__half>(g_VALh);
    __half* DOUTh = symT<__half>(g_DOUTh);
    __half* X2h   = symT<__half>(g_X2h);
    __half* HHh   = symT<__half>(g_HHh);
    __half* inwh  = symT<__half>(g_inwh);
    __half* outwh = symT<__half>(g_outwh);
    __half* valwh = symT<__half>(g_valwh);
    __half* oawh  = symT<__half>(g_oawh);
    __half* cowh  = symT<__half>(g_cowh);
    __half* l1wh  = symT<__half>(g_l1wh);
    __half* l2wh  = symT<__half>(g_l2wh);

    cudaFuncSetAttribute(flash_attn_kernel, cudaFuncAttributeMaxDynamicSharedMemorySize, FATT_SMEM);

    static cudaStream_t s2 = nullptr;
    static cudaEvent_t  eFork = nullptr, eJoin = nullptr;
    if (s2 == nullptr) {
        cudaStreamCreate(&s2);
        cudaEventCreateWithFlags(&eFork, cudaEventDisableTiming);
        cudaEventCreateWithFlags(&eJoin, cudaEventDisableTiming);
    }

    const int nElem = NR_ * D_;
    dim3 gQK(SQK / GBN, (NR_ + GBM - 1) / GBM);   // (4, 57)
    dim3 gP (D_ / GBN,  (NR_ + GBM - 1) / GBM);   // (2, 57)

    // ---- fork: side stream = post-attention weights + value branch ----
    cudaEventRecord(eFork, 0);
    cudaStreamWaitEvent(s2, eFork, 0);

    cvt_multi<<<512, 256, 0, s2>>>(out_w, outwh, D_ * D_, cout_w, cowh, D_ * D_,
                                   l1w, l1wh, DFF_ * D_, l2w, l2wh, D_ * DFF_);
    cvt_multi<<<2048, 256, 0, s2>>>(off_w, oawh, 256 * D_, aw_w, oawh + 256 * D_, 128 * D_,
                                    val_w, valwh, D_ * D_, memory, MEMh, S_ * B_ * D_);
    pack_bias<<<1, 384, 0, s2>>>(off_b, aw_b, oab);
    dim3 gV(D_ / GBN, (S_ * B_) / GBM);           // (2, 765)
    gemm_f16<false, true, __half><<<gV, 256, GEMM_SMEM, s2>>>(MEMh, valwh, val_b, VALh, S_ * B_, D_, D_, mask);
    cudaEventRecord(eJoin, s2);

    // ---- main stream: self-attention chain ----
    cvt_multi<<<256, 256>>>(in_w, inwh, 3 * D_ * D_, nullptr, nullptr, 0,
                            nullptr, nullptr, 0, nullptr, nullptr, 0);
    add2q_kernel<<<NR_, 256>>>(queries, pos, ADDQh, Qh, nElem);

    gemm_f16<false, false, __half><<<gQK, 256, GEMM_SMEM>>>(ADDQh, inwh, in_b, QKph, NR_, SQK, D_, nullptr);
    gemm_f16<false, false, __half><<<gP, 256, GEMM_SMEM>>>(Qh, inwh + 2 * D_ * D_, in_b + 2 * D_, Vh, NR_, D_, D_, nullptr);

    dim3 gFA((NQ_ + 63) / 64, B_ * H_);           // (15, 64)
    flash_attn_kernel<<<gFA, 256, FATT_SMEM>>>(QKph, Vh, SAph);

    cudaStreamWaitEvent(0, eJoin, 0);

    gemm_f16<false, false, float><<<gP, 256, GEMM_SMEM>>>(SAph, outwh, out_b, SA, NR_, D_, D_, nullptr);

    add_ln_kernel<<<NR_, 256>>>(queries, SA, n2g, n2b, X1, pos, QINh, nullptr);

    dim3 gOA((NOAW + GBN - 1) / GBN, (NR_ + GBM - 1) / GBM);   // (3, 57)
    gemm_f16<false, false, float><<<gOA, 256, GEMM_SMEM>>>(QINh, oawh, oab, OAW, NR_, NOAW, D_, nullptr);

    deform_sample_kernel<<<NR_, 256>>>(VALh, OAW, refpts, DOUTh);

    gemm_f16<false, false, float><<<gP, 256, GEMM_SMEM>>>(DOUTh, cowh, cout_b, CA, NR_, D_, D_, nullptr);

    add_ln_kernel<<<NR_, 256>>>(X1, CA, n1g, n1b, X2, nullptr, nullptr, X2h);

    dim3 gF1(DFF_ / GBN, (NR_ + GBM - 1) / GBM);  // (16, 57)
    gemm_f16<true, false, __half><<<gF1, 256, GEMM_SMEM>>>(X2h, l1wh, l1b, HHh, NR_, DFF_, D_, nullptr);
    gemm_f16<false, false, float><<<gP, 256, GEMM_SMEM>>>(HHh, l2wh, l2b, FF, NR_, D_, DFF_, nullptr);

    add_ln_kernel<<<NR_, 256>>>(X2, FF, n3g, n3b, (float*)d_out, nullptr, nullptr, nullptr);
}